// round 3
// baseline (speedup 1.0000x reference)
#include <cuda_runtime.h>
#include <cstdint>

// RandomizedOscillatorsNetwork: B=128, T=1024, I=64, H=512, dt=0.042
// R2: packed fma.rn.f32x2 inner loop (2x fp32 FMA rate), cluster(8) barrier
// replacing global red/poll, x-part matvec overlapped with barrier wait.
// Grid: 16 clusters x 8 CTAs. Cluster rank = column slice (64 cols),
// cluster id = batch group (8 batches).

#define DT_F      0.042f
#define B_        128
#define T_        1024
#define I_        64
#define H_        512
#define KAUG      576
#define NCOL      8
#define NGRP      16
#define BC        8             // batches per CTA
#define CC        64            // columns per CTA
#define WPITCH    580           // floats per W row: 4*odd -> conflict-free LDS.128
#define NTHREADS  512
#define KSLICES   16
#define HYCH      32            // hy k-chunk floats per slice (16*32 = 512)
#define XCH       4             // x  k-chunk floats per slice (16*4  = 64)
#define AROW16    (KAUG / 4)    // 144 16B-units per a row
#define WROW16    (WPITCH / 4)  // 145 16B-units per W row

typedef unsigned long long u64;

__device__ float g_hy_ex[2][NGRP][BC][H_];

__device__ __forceinline__ u64 ffma2(u64 a, u64 b, u64 c) {
    u64 d;
    asm("fma.rn.f32x2 %0, %1, %2, %3;" : "=l"(d) : "l"(a), "l"(b), "l"(c));
    return d;
}
__device__ __forceinline__ float hadd2(u64 v) {
    unsigned lo, hi;
    asm("mov.b64 {%0,%1}, %2;" : "=r"(lo), "=r"(hi) : "l"(v));
    return __uint_as_float(lo) + __uint_as_float(hi);
}

__global__ void __launch_bounds__(NTHREADS, 1) __cluster_dims__(NCOL, 1, 1)
ron_scan_kernel(const float* __restrict__ x,      // [B, T, I]
                const float* __restrict__ x2h,    // [I, H]
                const float* __restrict__ h2h,    // [H, H]
                const float* __restrict__ bias,   // [H]
                const float* __restrict__ gamma_, // [H]
                const float* __restrict__ eps_,   // [H]
                float* __restrict__ out,
                int write_tail)
{
    extern __shared__ float smem[];
    float* W_s     = smem;                       // [CC][WPITCH]
    float* a_s     = W_s + CC * WPITCH;          // [BC][KAUG]  hy | x_t
    float* partial = a_s + BC * KAUG;            // [KSLICES][BC][CC]

    const int tid = threadIdx.x;
    const int g   = blockIdx.x >> 3;             // batch group / cluster id
    const int j   = blockIdx.x & 7;              // column slice / cluster rank
    const int b0  = g * BC;
    const int cg0 = j * CC;

    const int ks  = tid >> 5;                    // k-slice 0..15
    const int c0  = tid & 31;                    // column (pair c0, c0+32)
    const int eb  = tid >> 6;                    // elementwise batch 0..7
    const int ec  = tid & 63;                    // elementwise column 0..63

    // ---- Prologue ----
    for (int idx = tid; idx < KAUG * CC; idx += NTHREADS) {
        int k  = idx >> 6;
        int cc = idx & 63;
        float w = (k < H_) ? h2h[(size_t)k * H_ + cg0 + cc]
                           : x2h[(size_t)(k - H_) * H_ + cg0 + cc];
        W_s[cc * WPITCH + k] = w;
    }
    for (int idx = tid; idx < BC * H_; idx += NTHREADS) {
        int b = idx >> 9, k = idx & 511;
        a_s[b * KAUG + k] = 0.0f;
    }
    a_s[eb * KAUG + H_ + ec] = x[((size_t)(b0 + eb) * T_ + 0) * I_ + ec];

    const float bia = bias  [cg0 + ec];
    const float gam = gamma_[cg0 + ec];
    const float ep  = eps_  [cg0 + ec];

    __syncthreads();

    float hy_reg = 0.0f, hz = 0.0f;

    const ulonglong2* W2 = reinterpret_cast<const ulonglong2*>(W_s);
    const ulonglong2* A2 = reinterpret_cast<const ulonglong2*>(a_s);
    const size_t w0base = (size_t)c0 * WROW16;
    const size_t w1base = w0base + (size_t)32 * WROW16;

    for (int t = 0; t < T_; t++) {
        // prefetch next-step input early (LDG latency hidden under matvec)
        float xnext = 0.0f;
        if (t + 1 < T_)
            xnext = x[((size_t)(b0 + eb) * T_ + (t + 1)) * I_ + ec];

        u64 acc0[BC], acc1[BC];
        #pragma unroll
        for (int b = 0; b < BC; b++) { acc0[b] = 0ULL; acc1[b] = 0ULL; }

        // ---- x-part matvec (K = 512..575): no dependence on incoming hy ----
        {
            const int o = 128 + ks;              // 16B-unit offset of this slice's x chunk
            ulonglong2 w0 = W2[w0base + o];
            ulonglong2 w1 = W2[w1base + o];
            #pragma unroll
            for (int b = 0; b < BC; b++) {
                ulonglong2 av = A2[b * AROW16 + o];
                acc0[b] = ffma2(av.x, w0.x, acc0[b]);
                acc0[b] = ffma2(av.y, w0.y, acc0[b]);
                acc1[b] = ffma2(av.x, w1.x, acc1[b]);
                acc1[b] = ffma2(av.y, w1.y, acc1[b]);
            }
        }

        // ---- wait for this step's hy data (overlapped with x-part above) ----
        if (t > 0) {
            asm volatile("barrier.cluster.wait.aligned;" ::: "memory");
            const int p = (t - 1) & 1;
            #pragma unroll
            for (int i = 0; i < 8; i++) {
                int idx = tid + i * NTHREADS;
                int b = idx >> 9, k = idx & 511;
                if ((k >> 6) != j)
                    a_s[b * KAUG + k] = __ldcg(&g_hy_ex[p][g][b][k]);
            }
            __syncthreads();
        }

        // ---- hy-part matvec (K = 0..511) ----
        {
            const int o = ks * (HYCH / 4);       // 16B-unit offset of hy chunk
            #pragma unroll
            for (int kb = 0; kb < HYCH / 4; kb++) {
                ulonglong2 w0 = W2[w0base + o + kb];
                ulonglong2 w1 = W2[w1base + o + kb];
                #pragma unroll
                for (int b = 0; b < BC; b++) {
                    ulonglong2 av = A2[b * AROW16 + o + kb];
                    acc0[b] = ffma2(av.x, w0.x, acc0[b]);
                    acc0[b] = ffma2(av.y, w0.y, acc0[b]);
                    acc1[b] = ffma2(av.x, w1.x, acc1[b]);
                    acc1[b] = ffma2(av.y, w1.y, acc1[b]);
                }
            }
        }

        // ---- k-split partial stores ----
        #pragma unroll
        for (int b = 0; b < BC; b++) {
            partial[ks * (BC * CC) + b * CC + c0]      = hadd2(acc0[b]);
            partial[ks * (BC * CC) + b * CC + c0 + 32] = hadd2(acc1[b]);
        }
        __syncthreads();

        // ---- reduce + oscillator update ----
        float v = 0.0f;
        #pragma unroll
        for (int s = 0; s < KSLICES; s++)
            v += partial[s * (BC * CC) + eb * CC + ec];

        float act = tanhf(v + bia);
        hz     = hz + DT_F * (act - gam * hy_reg - ep * hz);
        hy_reg = hy_reg + DT_F * hz;

        out[((size_t)(b0 + eb) * T_ + t) * H_ + cg0 + ec] = hy_reg;
        if (write_tail && t == T_ - 1)
            out[(size_t)B_ * T_ * H_ + (size_t)(b0 + eb) * H_ + cg0 + ec] = hy_reg;

        if (t + 1 == T_) break;

        // ---- publish + next-step staging ----
        a_s[eb * KAUG + cg0 + ec] = hy_reg;        // own hy slice (local)
        a_s[eb * KAUG + H_  + ec] = xnext;         // next x
        __stcg(&g_hy_ex[t & 1][g][eb][cg0 + ec], hy_reg);  // for peers (L2)

        asm volatile("barrier.cluster.arrive.aligned;" ::: "memory");
        __syncthreads();   // a_s writes visible CTA-wide before next x-part
    }
}

extern "C" void kernel_launch(void* const* d_in, const int* in_sizes, int n_in,
                              void* d_out, int out_size)
{
    const float* x      = (const float*)d_in[0];
    const float* x2h    = (const float*)d_in[1];
    const float* h2h    = (const float*)d_in[2];
    const float* bias   = (const float*)d_in[3];
    const float* gamma_ = (const float*)d_in[4];
    const float* eps_   = (const float*)d_in[5];
    float* out = (float*)d_out;

    const int smem_bytes = (CC * WPITCH + BC * KAUG + KSLICES * BC * CC) * 4; // 199,680
    cudaFuncSetAttribute(ron_scan_kernel,
                         cudaFuncAttributeMaxDynamicSharedMemorySize, smem_bytes);

    const int write_tail = (out_size > B_ * T_ * H_) ? 1 : 0;

    ron_scan_kernel<<<NGRP * NCOL, NTHREADS, smem_bytes>>>(
        x, x2h, h2h, bias, gamma_, eps_, out, write_tail);
}

// round 4
// speedup vs baseline: 1.6268x; 1.6268x over previous
#include <cuda_runtime.h>
#include <cstdint>

// RandomizedOscillatorsNetwork: B=128, T=1024, I=64, H=512, dt=0.042
// R3: revert ffma2 + cluster barrier (both regressed). Keep R1 FFMA float4
// matvec + global red/poll barrier, but restructure the loop to hide the
// sync chain: arrive ASAP after publish; out-STG/a_s staging after arrive;
// x-part matvec (no peer dependence) before the poll; refill before hy-part.

#define DT_F      0.042f
#define B_        128
#define T_        1024
#define I_        64
#define H_        512
#define KAUG      576           // H_ + I_
#define NCOL      8
#define NGRP      16
#define BC        8             // batches per CTA
#define CC        64            // columns per CTA
#define WPITCH    580           // floats per W row: 4*odd -> conflict-free LDS.128
#define NTHREADS  512
#define KSLICES   16
#define HY4       8             // float4 hy-chunk per slice (16*32 = 512 floats)
#define AROW4     (KAUG / 4)    // 144
#define WROW4     (WPITCH / 4)  // 145

__device__ unsigned g_bar[NGRP];
__device__ float    g_hy_ex[2][NGRP][BC][H_];

__device__ __forceinline__ unsigned ld_acquire_u32(const unsigned* p) {
    unsigned v;
    asm volatile("ld.acquire.gpu.u32 %0, [%1];" : "=r"(v) : "l"(p) : "memory");
    return v;
}
__device__ __forceinline__ void red_release_add(unsigned* p, unsigned v) {
    asm volatile("red.release.gpu.global.add.u32 [%0], %1;" :: "l"(p), "r"(v) : "memory");
}

__global__ void ron_init_kernel() {
    if (threadIdx.x < NGRP) g_bar[threadIdx.x] = 0u;
}

__global__ void __launch_bounds__(NTHREADS, 1)
ron_scan_kernel(const float* __restrict__ x,      // [B, T, I]
                const float* __restrict__ x2h,    // [I, H]
                const float* __restrict__ h2h,    // [H, H]
                const float* __restrict__ bias,   // [H]
                const float* __restrict__ gamma_, // [H]
                const float* __restrict__ eps_,   // [H]
                float* __restrict__ out,          // [B*T*H] (+ optional [B*H] tail)
                int write_tail)
{
    extern __shared__ float smem[];
    float* W_s     = smem;                        // [CC][WPITCH]  augmented weights, c-major
    float* a_s     = W_s + CC * WPITCH;           // [BC][KAUG]    hy | x_t
    float* partial = a_s + BC * KAUG;             // [KSLICES][BC][CC]

    const int tid = threadIdx.x;
    const int g   = blockIdx.x >> 3;
    const int j   = blockIdx.x & 7;
    const int b0  = g * BC;
    const int cg0 = j * CC;

    // matvec role
    const int ks  = tid >> 5;            // 0..15 k-slice
    const int c0  = tid & 31;            // local column (pair: c0, c0+32)
    // elementwise role
    const int eb  = tid >> 6;            // 0..7 local batch
    const int ec  = tid & 63;            // 0..63 local column

    // ---- Prologue ----
    for (int idx = tid; idx < KAUG * CC; idx += NTHREADS) {
        int k  = idx >> 6;
        int cc = idx & 63;
        float w = (k < H_) ? h2h[(size_t)k * H_ + cg0 + cc]
                           : x2h[(size_t)(k - H_) * H_ + cg0 + cc];
        W_s[cc * WPITCH + k] = w;
    }
    for (int idx = tid; idx < BC * H_; idx += NTHREADS) {
        int b = idx >> 9, k = idx & 511;
        a_s[b * KAUG + k] = 0.0f;
    }
    a_s[eb * KAUG + H_ + ec] = x[((size_t)(b0 + eb) * T_ + 0) * I_ + ec];

    const float bia = bias  [cg0 + ec];
    const float gam = gamma_[cg0 + ec];
    const float ep  = eps_  [cg0 + ec];

    __syncthreads();

    float hy_reg = 0.0f, hz = 0.0f;

    const float4* W4 = reinterpret_cast<const float4*>(W_s);
    const float4* A4 = reinterpret_cast<const float4*>(a_s);
    const size_t w0base = (size_t)c0 * WROW4;
    const size_t w1base = w0base + (size_t)32 * WROW4;

    for (int t = 0; t < T_; t++) {
        // prefetch next-step input (LDG latency hidden under matvec)
        float xnext = 0.0f;
        if (t + 1 < T_)
            xnext = x[((size_t)(b0 + eb) * T_ + (t + 1)) * I_ + ec];

        float acc0[BC], acc1[BC];
        #pragma unroll
        for (int b = 0; b < BC; b++) { acc0[b] = 0.0f; acc1[b] = 0.0f; }

        // ---- x-part matvec (K = 512..575): independent of peers' hy ----
        {
            const int o4 = (H_ / 4) + ks;          // float4 index: 128 + ks
            float4 w0 = W4[w0base + o4];
            float4 w1 = W4[w1base + o4];
            #pragma unroll
            for (int b = 0; b < BC; b++) {
                float4 av = A4[b * AROW4 + o4];
                acc0[b] = fmaf(av.x, w0.x, acc0[b]);
                acc0[b] = fmaf(av.y, w0.y, acc0[b]);
                acc0[b] = fmaf(av.z, w0.z, acc0[b]);
                acc0[b] = fmaf(av.w, w0.w, acc0[b]);
                acc1[b] = fmaf(av.x, w1.x, acc1[b]);
                acc1[b] = fmaf(av.y, w1.y, acc1[b]);
                acc1[b] = fmaf(av.z, w1.z, acc1[b]);
                acc1[b] = fmaf(av.w, w1.w, acc1[b]);
            }
        }

        // ---- wait for peers' hy (published end of step t-1), then refill ----
        if (t > 0) {
            if (tid == 0) {
                const unsigned target = (unsigned)(NCOL * t);
                while (ld_acquire_u32(&g_bar[g]) < target) { }
            }
            __syncthreads();
            const int p = (t - 1) & 1;
            #pragma unroll
            for (int i = 0; i < 8; i++) {
                int idx = tid + i * NTHREADS;
                int b = idx >> 9, k = idx & 511;
                if ((k >> 6) != j)
                    a_s[b * KAUG + k] = __ldcg(&g_hy_ex[p][g][b][k]);
            }
            __syncthreads();
        }

        // ---- hy-part matvec (K = 0..511) ----
        {
            const int o4 = ks * HY4;
            #pragma unroll
            for (int kb = 0; kb < HY4; kb++) {
                float4 w0 = W4[w0base + o4 + kb];
                float4 w1 = W4[w1base + o4 + kb];
                #pragma unroll
                for (int b = 0; b < BC; b++) {
                    float4 av = A4[b * AROW4 + o4 + kb];
                    acc0[b] = fmaf(av.x, w0.x, acc0[b]);
                    acc0[b] = fmaf(av.y, w0.y, acc0[b]);
                    acc0[b] = fmaf(av.z, w0.z, acc0[b]);
                    acc0[b] = fmaf(av.w, w0.w, acc0[b]);
                    acc1[b] = fmaf(av.x, w1.x, acc1[b]);
                    acc1[b] = fmaf(av.y, w1.y, acc1[b]);
                    acc1[b] = fmaf(av.z, w1.z, acc1[b]);
                    acc1[b] = fmaf(av.w, w1.w, acc1[b]);
                }
            }
        }

        // ---- k-split partial stores + reduce ----
        #pragma unroll
        for (int b = 0; b < BC; b++) {
            partial[ks * (BC * CC) + b * CC + c0]      = acc0[b];
            partial[ks * (BC * CC) + b * CC + c0 + 32] = acc1[b];
        }
        __syncthreads();

        float v = 0.0f;
        #pragma unroll
        for (int s = 0; s < KSLICES; s++)
            v += partial[s * (BC * CC) + eb * CC + ec];

        // ---- oscillator update ----
        float act = tanhf(v + bia);
        hz     = hz + DT_F * (act - gam * hy_reg - ep * hz);
        hy_reg = hy_reg + DT_F * hz;

        if (t + 1 == T_) {
            out[((size_t)(b0 + eb) * T_ + t) * H_ + cg0 + ec] = hy_reg;
            if (write_tail)
                out[(size_t)B_ * T_ * H_ + (size_t)(b0 + eb) * H_ + cg0 + ec] = hy_reg;
            break;
        }

        // ---- publish + arrive FIRST (peers' critical path) ----
        __stcg(&g_hy_ex[t & 1][g][eb][cg0 + ec], hy_reg);
        __threadfence();            // order all threads' stcg before the release
        __syncthreads();
        if (tid == 0) red_release_add(&g_bar[g], 1u);

        // ---- off-critical-path work after arrive ----
        out[((size_t)(b0 + eb) * T_ + t) * H_ + cg0 + ec] = hy_reg;
        a_s[eb * KAUG + cg0 + ec] = hy_reg;      // own hy slice (local)
        a_s[eb * KAUG + H_  + ec] = xnext;       // next x
        __syncthreads();                         // a_s visible before next x-part
    }
}

extern "C" void kernel_launch(void* const* d_in, const int* in_sizes, int n_in,
                              void* d_out, int out_size)
{
    const float* x      = (const float*)d_in[0];
    const float* x2h    = (const float*)d_in[1];
    const float* h2h    = (const float*)d_in[2];
    const float* bias   = (const float*)d_in[3];
    const float* gamma_ = (const float*)d_in[4];
    const float* eps_   = (const float*)d_in[5];
    float* out = (float*)d_out;

    const int smem_bytes = (CC * WPITCH + BC * KAUG + KSLICES * BC * CC) * 4; // 199,680
    cudaFuncSetAttribute(ron_scan_kernel,
                         cudaFuncAttributeMaxDynamicSharedMemorySize, smem_bytes);

    const int write_tail = (out_size > B_ * T_ * H_) ? 1 : 0;

    ron_init_kernel<<<1, 32>>>();
    ron_scan_kernel<<<NGRP * NCOL, NTHREADS, smem_bytes>>>(
        x, x2h, h2h, bias, gamma_, eps_, out, write_tail);
}

// round 10
// speedup vs baseline: 1.7954x; 1.1037x over previous
#include <cuda_runtime.h>
#include <cstdint>

// RandomizedOscillatorsNetwork: B=128, T=1024, I=64, H=512, dt=0.042
// R4 (resubmit — prior bench was an infra failure, kernel never measured)
// = R1 skeleton (best: 3894us) + two surgical changes:
//  (1) publish/arrive BEFORE out-STG & staging; out-STG overlaps tid0 poll
//  (2) refill as 2x coalesced float4 ldcg per thread (all 8 slices, no guard,
//      no own-slice STS)
// Monolithic matvec, 4 syncs/step, no threadfence (R1-verified protocol).

#define DT_F      0.042f
#define B_        128
#define T_        1024
#define I_        64
#define H_        512
#define KAUG      576           // H_ + I_
#define NCOL      8
#define NGRP      16
#define BC        8             // batches per CTA
#define CC        64            // columns per CTA
#define WPITCH    580           // 4*odd -> conflict-free float4 LDS
#define NTHREADS  512
#define KSLICES   16
#define KCHUNK4   9             // float4 per k-slice (36 floats)
#define AROW4     (KAUG / 4)    // 144
#define WROW4     (WPITCH / 4)  // 145

__device__ unsigned g_bar[NGRP];
__device__ float    g_hy_ex[2][NGRP][BC][H_];

__device__ __forceinline__ unsigned ld_acquire_u32(const unsigned* p) {
    unsigned v;
    asm volatile("ld.acquire.gpu.u32 %0, [%1];" : "=r"(v) : "l"(p) : "memory");
    return v;
}
__device__ __forceinline__ void red_release_add(unsigned* p, unsigned v) {
    asm volatile("red.release.gpu.global.add.u32 [%0], %1;" :: "l"(p), "r"(v) : "memory");
}

__global__ void ron_init_kernel() {
    if (threadIdx.x < NGRP) g_bar[threadIdx.x] = 0u;
}

__global__ void __launch_bounds__(NTHREADS, 1)
ron_scan_kernel(const float* __restrict__ x,      // [B, T, I]
                const float* __restrict__ x2h,    // [I, H]
                const float* __restrict__ h2h,    // [H, H]
                const float* __restrict__ bias,   // [H]
                const float* __restrict__ gamma_, // [H]
                const float* __restrict__ eps_,   // [H]
                float* __restrict__ out,          // [B*T*H] (+ optional [B*H] tail)
                int write_tail)
{
    extern __shared__ float smem[];
    float* W_s     = smem;                        // [CC][WPITCH] augmented weights, c-major
    float* a_s     = W_s + CC * WPITCH;           // [BC][KAUG]   hy | x_t
    float* partial = a_s + BC * KAUG;             // [KSLICES][BC][CC]

    const int tid = threadIdx.x;
    const int g   = blockIdx.x >> 3;
    const int j   = blockIdx.x & 7;
    const int b0  = g * BC;
    const int cg0 = j * CC;

    // matvec role
    const int ks  = tid >> 5;            // 0..15 k-slice
    const int c0  = tid & 31;            // local column (pair: c0, c0+32)
    // elementwise role
    const int eb  = tid >> 6;            // 0..7 local batch
    const int ec  = tid & 63;            // 0..63 local column

    // ---- Prologue ----
    for (int idx = tid; idx < KAUG * CC; idx += NTHREADS) {
        int k  = idx >> 6;
        int cc = idx & 63;
        float w = (k < H_) ? h2h[(size_t)k * H_ + cg0 + cc]
                           : x2h[(size_t)(k - H_) * H_ + cg0 + cc];
        W_s[cc * WPITCH + k] = w;
    }
    for (int idx = tid; idx < BC * H_; idx += NTHREADS) {
        int b = idx >> 9, k = idx & 511;
        a_s[b * KAUG + k] = 0.0f;
    }
    a_s[eb * KAUG + H_ + ec] = x[((size_t)(b0 + eb) * T_ + 0) * I_ + ec];

    const float bia = bias  [cg0 + ec];
    const float gam = gamma_[cg0 + ec];
    const float ep  = eps_  [cg0 + ec];

    __syncthreads();

    float hy_reg = 0.0f, hz = 0.0f;

    const float4* W4 = reinterpret_cast<const float4*>(W_s);
    const float4* A4 = reinterpret_cast<const float4*>(a_s);
    float4*       A4w = reinterpret_cast<float4*>(a_s);
    const size_t w0base = (size_t)c0 * WROW4 + (size_t)ks * KCHUNK4;
    const size_t w1base = w0base + (size_t)32 * WROW4;

    for (int t = 0; t < T_; t++) {
        // prefetch next-step input (LDG latency hidden under matvec)
        float xnext = 0.0f;
        if (t + 1 < T_)
            xnext = x[((size_t)(b0 + eb) * T_ + (t + 1)) * I_ + ec];

        // ---- Matvec: Tc=2 columns x Tb=8 batches per thread over its k-chunk ----
        float acc0[BC], acc1[BC];
        #pragma unroll
        for (int b = 0; b < BC; b++) { acc0[b] = 0.0f; acc1[b] = 0.0f; }

        #pragma unroll
        for (int kb = 0; kb < KCHUNK4; kb++) {
            float4 w0 = W4[w0base + kb];
            float4 w1 = W4[w1base + kb];
            #pragma unroll
            for (int b = 0; b < BC; b++) {
                float4 av = A4[b * AROW4 + ks * KCHUNK4 + kb];
                acc0[b] = fmaf(av.x, w0.x, acc0[b]);
                acc0[b] = fmaf(av.y, w0.y, acc0[b]);
                acc0[b] = fmaf(av.z, w0.z, acc0[b]);
                acc0[b] = fmaf(av.w, w0.w, acc0[b]);
                acc1[b] = fmaf(av.x, w1.x, acc1[b]);
                acc1[b] = fmaf(av.y, w1.y, acc1[b]);
                acc1[b] = fmaf(av.z, w1.z, acc1[b]);
                acc1[b] = fmaf(av.w, w1.w, acc1[b]);
            }
        }

        // ---- k-split partial stores ----
        #pragma unroll
        for (int b = 0; b < BC; b++) {
            partial[ks * (BC * CC) + b * CC + c0]      = acc0[b];
            partial[ks * (BC * CC) + b * CC + c0 + 32] = acc1[b];
        }
        __syncthreads();   // #1

        // ---- reduce + oscillator update ----
        float v = 0.0f;
        #pragma unroll
        for (int s = 0; s < KSLICES; s++)
            v += partial[s * (BC * CC) + eb * CC + ec];

        float act = tanhf(v + bia);
        hz     = hz + DT_F * (act - gam * hy_reg - ep * hz);
        hy_reg = hy_reg + DT_F * hz;

        if (t + 1 == T_) {
            out[((size_t)(b0 + eb) * T_ + t) * H_ + cg0 + ec] = hy_reg;
            if (write_tail)
                out[(size_t)B_ * T_ * H_ + (size_t)(b0 + eb) * H_ + cg0 + ec] = hy_reg;
            break;
        }

        // ---- publish + arrive FIRST (global critical path for peers) ----
        __stcg(&g_hy_ex[t & 1][g][eb][cg0 + ec], hy_reg);
        __syncthreads();   // #2: all stcg issued before the release
        if (tid == 0) {
            red_release_add(&g_bar[g], 1u);
            const unsigned target = (unsigned)(NCOL * (t + 1));
            while (ld_acquire_u32(&g_bar[g]) < target) { }
        }
        // overlap with tid0's poll: own-work off the peers' critical path
        out[((size_t)(b0 + eb) * T_ + t) * H_ + cg0 + ec] = hy_reg;
        a_s[eb * KAUG + H_ + ec] = xnext;
        __syncthreads();   // #3: poll done -> peers' hy visible

        // ---- refill all 8 hy slices: 2 coalesced float4 loads per thread ----
        {
            const float4* G4 = reinterpret_cast<const float4*>(&g_hy_ex[t & 1][g][0][0]);
            #pragma unroll
            for (int i = 0; i < 2; i++) {
                int idx = tid + i * NTHREADS;          // float4 index 0..1023
                int b   = idx >> 7;                    // 128 float4 per row
                int k4  = idx & 127;
                A4w[b * AROW4 + k4] = __ldcg(&G4[idx]);
            }
        }
        __syncthreads();   // #4: a_s ready for next matvec
    }
}

extern "C" void kernel_launch(void* const* d_in, const int* in_sizes, int n_in,
                              void* d_out, int out_size)
{
    const float* x      = (const float*)d_in[0];
    const float* x2h    = (const float*)d_in[1];
    const float* h2h    = (const float*)d_in[2];
    const float* bias   = (const float*)d_in[3];
    const float* gamma_ = (const float*)d_in[4];
    const float* eps_   = (const float*)d_in[5];
    float* out = (float*)d_out;

    const int smem_bytes = (CC * WPITCH + BC * KAUG + KSLICES * BC * CC) * 4; // 199,680
    cudaFuncSetAttribute(ron_scan_kernel,
                         cudaFuncAttributeMaxDynamicSharedMemorySize, smem_bytes);

    const int write_tail = (out_size > B_ * T_ * H_) ? 1 : 0;

    ron_init_kernel<<<1, 32>>>();
    ron_scan_kernel<<<NGRP * NCOL, NTHREADS, smem_bytes>>>(
        x, x2h, h2h, bias, gamma_, eps_, out, write_tail);
}